// round 1
// baseline (speedup 1.0000x reference)
#include <cuda_runtime.h>
#include <cuda_fp16.h>
#include <cstdint>

#define B_ROWS 65536
#define D_IN   784
#define D_H    300
#define DHP    304      // padded h width (stride), multiple of 16
#define BNP    320      // padded binarized-W1 rows (multiple of 8*#ntiles)
#define D_OUT  10
#define EPSV   1e-5f
#define STATS1_BLOCKS 128
#define G2_BLOCKS (B_ROWS / 8)

// ---------------- scratch (static device globals; no runtime alloc) -------
__device__ __align__(16) __half g_Bh1[BNP * D_IN];          // sign(W1), fp16, rows>=300 zero
__device__ __align__(16) float  g_B2f[D_OUT * DHP];         // sign(W2), fp32, cols>=300 zero
__device__ __align__(16) __half g_h[(size_t)B_ROWS * DHP];  // layer-1 pre-BN output (fp16)
__device__ __align__(16) float  g_part1[2 * STATS1_BLOCKS * DHP];
__device__ __align__(16) float  g_ab1[2 * DHP];             // BN1 folded affine a,b
__device__ __align__(16) float  g_part2[G2_BLOCKS * 20];
__device__ __align__(16) float  g_ab2[2 * D_OUT];           // BN2 affine

// ---------------- prep: binarize weights ----------------------------------
__global__ void prep_kernel(const float* __restrict__ W1, const float* __restrict__ W2) {
    int i = blockIdx.x * blockDim.x + threadIdx.x;
    const int n1 = BNP * D_IN;
    if (i < n1) {
        int n = i / D_IN, k = i - n * D_IN;
        float v = 0.f;
        if (n < D_H) v = (W1[n * D_IN + k] >= 0.f) ? 1.f : -1.f;
        g_Bh1[i] = __float2half_rn(v);
    } else {
        int j = i - n1;
        if (j < D_OUT * DHP) {
            int n = j / DHP, k = j - n * DHP;
            float v = 0.f;
            if (k < D_H) v = (W2[n * D_H + k] >= 0.f) ? 1.f : -1.f;
            g_B2f[j] = v;
        }
    }
}

// ---------------- GEMM1: h = x @ sign(W1)^T  (fp16 HMMA, fp32 accum) ------
// Block tile: 64 rows x 320 cols (full N), BK=16, 256 threads (8 warps: 4m x 2n).
// Warp tile: 16 x 160 = 20 n-tiles of m16n8k16. 80 fp32 accumulators/thread.
__global__ __launch_bounds__(256, 2) void gemm1_kernel(const float* __restrict__ x) {
    __shared__ __align__(16) __half As[64][24];    // +8 halves pad: conflict-free frag loads
    __shared__ __align__(16) __half Bs[BNP][24];

    const int tid  = threadIdx.x;
    const int wid  = tid >> 5, lane = tid & 31;
    const int wm   = wid & 3,  wn   = wid >> 2;     // 4 x 2 warp grid
    const int g    = lane >> 2, tg  = lane & 3;     // mma group / thread-in-group
    const int m0   = blockIdx.x * 64;

    float acc[20][4];
#pragma unroll
    for (int i = 0; i < 20; i++)
#pragma unroll
        for (int j = 0; j < 4; j++) acc[i][j] = 0.f;

    // global->shared staging map
    const int arow  = tid >> 2;            // 0..63
    const int acol  = (tid & 3) * 4;       // 0,4,8,12 (floats)
    const int brow0 = tid >> 2;            // + i*64, i<5 -> 0..319
    const int bq    = (tid & 3) * 4;       // halves

    const float* aBase = x + (size_t)(m0 + arow) * D_IN + acol;

    // prefetch kb = 0
    float4 aReg = *(const float4*)(aBase);
    uint2  bReg[5];
#pragma unroll
    for (int i = 0; i < 5; i++)
        bReg[i] = *(const uint2*)(g_Bh1 + (size_t)(brow0 + i * 64) * D_IN + bq);

    for (int kb = 0; kb < D_IN / 16; kb++) {
        // regs -> shared (A converted to fp16)
        __half2* ad = (__half2*)&As[arow][acol];
        ad[0] = __floats2half2_rn(aReg.x, aReg.y);
        ad[1] = __floats2half2_rn(aReg.z, aReg.w);
#pragma unroll
        for (int i = 0; i < 5; i++)
            *(uint2*)&Bs[brow0 + i * 64][bq] = bReg[i];
        __syncthreads();

        // prefetch next tile into regs (overlaps with mma below)
        if (kb < D_IN / 16 - 1) {
            const int k0 = (kb + 1) * 16;
            aReg = *(const float4*)(aBase + k0);
#pragma unroll
            for (int i = 0; i < 5; i++)
                bReg[i] = *(const uint2*)(g_Bh1 + (size_t)(brow0 + i * 64) * D_IN + k0 + bq);
        }

        // compute: one k16 step, 20 n-tiles
        const int ra = wm * 16 + g;
        const uint32_t a0 = *(const uint32_t*)&As[ra    ][tg * 2    ];
        const uint32_t a1 = *(const uint32_t*)&As[ra + 8][tg * 2    ];
        const uint32_t a2 = *(const uint32_t*)&As[ra    ][tg * 2 + 8];
        const uint32_t a3 = *(const uint32_t*)&As[ra + 8][tg * 2 + 8];
#pragma unroll
        for (int nt = 0; nt < 20; nt++) {
            const int rb = wn * 160 + nt * 8 + g;
            const uint32_t b0 = *(const uint32_t*)&Bs[rb][tg * 2    ];
            const uint32_t b1 = *(const uint32_t*)&Bs[rb][tg * 2 + 8];
            asm volatile(
                "mma.sync.aligned.m16n8k16.row.col.f32.f16.f16.f32 "
                "{%0,%1,%2,%3}, {%4,%5,%6,%7}, {%8,%9}, {%0,%1,%2,%3};\n"
                : "+f"(acc[nt][0]), "+f"(acc[nt][1]), "+f"(acc[nt][2]), "+f"(acc[nt][3])
                : "r"(a0), "r"(a1), "r"(a2), "r"(a3), "r"(b0), "r"(b1));
        }
        __syncthreads();
    }

    // epilogue: h (fp16), cols < DHP only (300..303 are exact zeros from zero B rows)
    const int row0 = m0 + wm * 16 + g;
#pragma unroll
    for (int nt = 0; nt < 20; nt++) {
        const int col = wn * 160 + nt * 8 + tg * 2;
        if (col < DHP) {
            *(__half2*)&g_h[(size_t)row0 * DHP + col]       = __floats2half2_rn(acc[nt][0], acc[nt][1]);
            *(__half2*)&g_h[(size_t)(row0 + 8) * DHP + col] = __floats2half2_rn(acc[nt][2], acc[nt][3]);
        }
    }
}

// ---------------- BN1 stats: deterministic 2-stage column reduction -------
__global__ void stats1_kernel() {
    const int t = threadIdx.x;             // blockDim = 320
    if (t >= DHP) return;
    const size_t r0 = (size_t)blockIdx.x * (B_ROWS / STATS1_BLOCKS);
    float s = 0.f, q = 0.f;
    for (int r = 0; r < B_ROWS / STATS1_BLOCKS; r++) {
        float v = __half2float(g_h[(r0 + r) * DHP + t]);
        s += v; q += v * v;
    }
    g_part1[blockIdx.x * DHP + t] = s;
    g_part1[STATS1_BLOCKS * DHP + blockIdx.x * DHP + t] = q;
}

__global__ void reduce1_kernel(const float* __restrict__ gamma1, const float* __restrict__ beta1) {
    const int t = threadIdx.x;             // blockDim = 320
    if (t >= DHP) return;
    float s = 0.f, q = 0.f;
    for (int i = 0; i < STATS1_BLOCKS; i++) {
        s += g_part1[i * DHP + t];
        q += g_part1[STATS1_BLOCKS * DHP + i * DHP + t];
    }
    const float inv = 1.f / (float)B_ROWS;
    const float mean = s * inv;
    const float var  = q * inv - mean * mean;
    float a = 0.f, b = 0.f;
    if (t < D_H) {
        a = gamma1[t] * rsqrtf(var + EPSV);
        b = beta1[t] - mean * a;
    }
    g_ab1[t] = a;
    g_ab1[DHP + t] = b;
}

// ---------------- GEMM2: o = BN1(h) @ sign(W2)^T, + BN2 partials ----------
// warp-per-row; folds BN1 via t = h*a + b (a,b zero on padded cols).
__global__ __launch_bounds__(256) void gemm2_kernel(float* __restrict__ out) {
    __shared__ float s2s[D_OUT * DHP];
    __shared__ float as[DHP], bs[DHP];
    __shared__ float osh[8][D_OUT];

    const int tid = threadIdx.x;
    for (int i = tid; i < D_OUT * DHP; i += 256) s2s[i] = g_B2f[i];
    for (int i = tid; i < DHP; i += 256) { as[i] = g_ab1[i]; bs[i] = g_ab1[DHP + i]; }
    __syncthreads();

    const int w = tid >> 5, l = tid & 31;
    const size_t r = (size_t)blockIdx.x * 8 + w;

    float acc[D_OUT];
#pragma unroll
    for (int j = 0; j < D_OUT; j++) acc[j] = 0.f;

#pragma unroll
    for (int i = 0; i < 10; i++) {         // ceil(304/32)
        const int k = l + i * 32;
        if (k < DHP) {
            const float hv = __half2float(g_h[r * DHP + k]);
            const float tv = fmaf(hv, as[k], bs[k]);
#pragma unroll
            for (int j = 0; j < D_OUT; j++)
                acc[j] = fmaf(tv, s2s[j * DHP + k], acc[j]);
        }
    }
#pragma unroll
    for (int j = 0; j < D_OUT; j++)
#pragma unroll
        for (int o = 16; o > 0; o >>= 1)
            acc[j] += __shfl_xor_sync(0xffffffffu, acc[j], o);

    if (l < D_OUT) {
        out[r * D_OUT + l] = acc[l];
        osh[w][l] = acc[l];
    }
    __syncthreads();
    if (tid < D_OUT) {                      // deterministic per-block partials
        float s = 0.f, q = 0.f;
#pragma unroll
        for (int w2 = 0; w2 < 8; w2++) { float v = osh[w2][tid]; s += v; q += v * v; }
        g_part2[blockIdx.x * 20 + tid] = s;
        g_part2[blockIdx.x * 20 + D_OUT + tid] = q;
    }
}

__global__ void reduce2_kernel(const float* __restrict__ gamma2, const float* __restrict__ beta2) {
    __shared__ float ss[256], qq[256];
    const int t = threadIdx.x, j = blockIdx.x;   // grid = 10
    float s = 0.f, q = 0.f;
    for (int i = t; i < G2_BLOCKS; i += 256) {
        s += g_part2[i * 20 + j];
        q += g_part2[i * 20 + D_OUT + j];
    }
    ss[t] = s; qq[t] = q; __syncthreads();
    for (int o = 128; o > 0; o >>= 1) {
        if (t < o) { ss[t] += ss[t + o]; qq[t] += qq[t + o]; }
        __syncthreads();
    }
    if (t == 0) {
        const float inv = 1.f / (float)B_ROWS;
        const float mean = ss[0] * inv;
        const float var  = qq[0] * inv - mean * mean;
        const float a = gamma2[j] * rsqrtf(var + EPSV);
        g_ab2[j] = a;
        g_ab2[D_OUT + j] = beta2[j] - mean * a;
    }
}

__global__ void apply_kernel(float* __restrict__ out) {
    const int i = blockIdx.x * blockDim.x + threadIdx.x;
    if (i < B_ROWS * D_OUT) {
        const int j = i % D_OUT;
        out[i] = fmaf(out[i], g_ab2[j], g_ab2[D_OUT + j]);
    }
}

// ---------------- launch ---------------------------------------------------
extern "C" void kernel_launch(void* const* d_in, const int* in_sizes, int n_in,
                              void* d_out, int out_size) {
    const float* x      = (const float*)d_in[0];
    const float* W1     = (const float*)d_in[1];
    const float* gamma1 = (const float*)d_in[2];
    const float* beta1  = (const float*)d_in[3];
    const float* W2     = (const float*)d_in[4];
    const float* gamma2 = (const float*)d_in[5];
    const float* beta2  = (const float*)d_in[6];
    float* out = (float*)d_out;

    const int prepN = BNP * D_IN + D_OUT * DHP;
    prep_kernel<<<(prepN + 255) / 256, 256>>>(W1, W2);
    gemm1_kernel<<<B_ROWS / 64, 256>>>(x);
    stats1_kernel<<<STATS1_BLOCKS, 320>>>();
    reduce1_kernel<<<1, 320>>>(gamma1, beta1);
    gemm2_kernel<<<G2_BLOCKS, 256>>>(out);
    reduce2_kernel<<<D_OUT, 256>>>(gamma2, beta2);
    apply_kernel<<<(B_ROWS * D_OUT + 255) / 256, 256>>>(out);
}

// round 2
// speedup vs baseline: 1.2704x; 1.2704x over previous
#include <cuda_runtime.h>
#include <cuda_fp16.h>
#include <cstdint>

#define B_ROWS 65536
#define D_IN   784
#define D_H    300
#define DHP    304      // padded h width (stride), multiple of 16
#define BNP    320      // padded binarized-W1 rows
#define D_OUT  10
#define EPSV   1e-5f
#define G1_BLOCKS (B_ROWS / 128)   // 512
#define G2_BLOCKS (B_ROWS / 128)   // 512

// ---------------- scratch (static device globals; no runtime alloc) -------
__device__ __align__(16) __half g_Bh1[BNP * D_IN];          // sign(W1) fp16, rows>=300 zero
__device__ __align__(16) __half g_B2h[16 * DHP];            // sign(W2) fp16 16x304, padded zero
__device__ __align__(16) __half g_h[(size_t)B_ROWS * DHP];  // layer-1 pre-BN output (fp16)
__device__ __align__(16) float  g_part1s[DHP * G1_BLOCKS];  // BN1 sum partials [col][blk]
__device__ __align__(16) float  g_part1q[DHP * G1_BLOCKS];  // BN1 sq  partials [col][blk]
__device__ __align__(16) float  g_ab1[2 * DHP];             // BN1 folded affine a,b
__device__ __align__(16) float  g_part2[G2_BLOCKS * 20];
__device__ __align__(16) float  g_ab2[2 * D_OUT];           // BN2 affine

#define MMA16816(acc, a0,a1,a2,a3, b0,b1)                                      \
    asm volatile(                                                              \
        "mma.sync.aligned.m16n8k16.row.col.f32.f16.f16.f32 "                   \
        "{%0,%1,%2,%3}, {%4,%5,%6,%7}, {%8,%9}, {%0,%1,%2,%3};\n"              \
        : "+f"(acc[0]), "+f"(acc[1]), "+f"(acc[2]), "+f"(acc[3])               \
        : "r"(a0), "r"(a1), "r"(a2), "r"(a3), "r"(b0), "r"(b1))

// ---------------- prep: binarize weights ----------------------------------
__global__ void prep_kernel(const float* __restrict__ W1, const float* __restrict__ W2) {
    int i = blockIdx.x * blockDim.x + threadIdx.x;
    const int n1 = BNP * D_IN;
    if (i < n1) {
        int n = i / D_IN, k = i - n * D_IN;
        float v = 0.f;
        if (n < D_H) v = (W1[n * D_IN + k] >= 0.f) ? 1.f : -1.f;
        g_Bh1[i] = __float2half_rn(v);
    } else {
        int j = i - n1;
        if (j < 16 * DHP) {
            int r = j / DHP, c = j - r * DHP;
            float v = 0.f;
            if (r < D_OUT && c < D_H) v = (W2[r * D_H + c] >= 0.f) ? 1.f : -1.f;
            g_B2h[j] = __float2half_rn(v);
        }
    }
}

// ---------------- GEMM1: h = x @ sign(W1)^T + fused BN1 column partials ---
// Block tile 128x320, BK=16, 512 threads (16 warps: 4m x 4n), double-buffered
// smem, one __syncthreads per k-iter. Warp tile 32x80 -> 2x10 mmas.
__global__ __launch_bounds__(512, 1) void gemm1_kernel(const float* __restrict__ x) {
    __shared__ __align__(16) __half As[2][128][24];   // 12,288 B (pad 24 -> conflict-free)
    __shared__ __align__(16) __half Bs[2][320][24];   // 30,720 B

    const int tid  = threadIdx.x;
    const int wid  = tid >> 5, lane = tid & 31;
    const int wm   = wid & 3,  wn   = wid >> 2;       // 4 x 4 warp grid
    const int g    = lane >> 2, tg  = lane & 3;
    const int m0   = blockIdx.x * 128;

    float acc[2][10][4];
#pragma unroll
    for (int mt = 0; mt < 2; mt++)
#pragma unroll
        for (int nt = 0; nt < 10; nt++)
#pragma unroll
            for (int e = 0; e < 4; e++) acc[mt][nt][e] = 0.f;

    // staging maps
    const int arow = tid >> 2;                 // 0..127
    const int acol = (tid & 3) * 4;            // floats
    const int brow0 = tid >> 1, bc0 = (tid & 1) * 8;          // uint4 #1 (idx=tid<640)
    const int idx1 = tid + 512;
    const bool bp1 = idx1 < 640;
    const int brow1 = idx1 >> 1, bc1 = (idx1 & 1) * 8;        // uint4 #2

    const float*  aBase  = x + (size_t)(m0 + arow) * D_IN + acol;
    const __half* b0Base = g_Bh1 + (size_t)brow0 * D_IN + bc0;
    const __half* b1Base = g_Bh1 + (size_t)brow1 * D_IN + bc1;

    // prefetch kb=0
    float4 aReg = *(const float4*)aBase;
    uint4  bReg0 = *(const uint4*)b0Base;
    uint4  bReg1 = make_uint4(0, 0, 0, 0);
    if (bp1) bReg1 = *(const uint4*)b1Base;

    // stage 0
    {
        __half2* ad = (__half2*)&As[0][arow][acol];
        ad[0] = __floats2half2_rn(aReg.x, aReg.y);
        ad[1] = __floats2half2_rn(aReg.z, aReg.w);
        *(uint4*)&Bs[0][brow0][bc0] = bReg0;
        if (bp1) *(uint4*)&Bs[0][brow1][bc1] = bReg1;
    }
    __syncthreads();

    const int NK = D_IN / 16;   // 49
    for (int kb = 0; kb < NK; kb++) {
        const int cur = kb & 1, nxt = cur ^ 1;
        if (kb < NK - 1) {
            const int k0 = (kb + 1) * 16;
            aReg = *(const float4*)(aBase + k0);
            bReg0 = *(const uint4*)(b0Base + k0);
            if (bp1) bReg1 = *(const uint4*)(b1Base + k0);
        }
        // compute
        uint32_t af[2][4];
#pragma unroll
        for (int mt = 0; mt < 2; mt++) {
            const int ra = wm * 32 + mt * 16 + g;
            af[mt][0] = *(const uint32_t*)&As[cur][ra    ][tg * 2    ];
            af[mt][1] = *(const uint32_t*)&As[cur][ra + 8][tg * 2    ];
            af[mt][2] = *(const uint32_t*)&As[cur][ra    ][tg * 2 + 8];
            af[mt][3] = *(const uint32_t*)&As[cur][ra + 8][tg * 2 + 8];
        }
#pragma unroll
        for (int nt = 0; nt < 10; nt++) {
            const int rb = wn * 80 + nt * 8 + g;
            const uint32_t b0v = *(const uint32_t*)&Bs[cur][rb][tg * 2    ];
            const uint32_t b1v = *(const uint32_t*)&Bs[cur][rb][tg * 2 + 8];
            MMA16816(acc[0][nt], af[0][0], af[0][1], af[0][2], af[0][3], b0v, b1v);
            MMA16816(acc[1][nt], af[1][0], af[1][1], af[1][2], af[1][3], b0v, b1v);
        }
        if (kb < NK - 1) {
            __half2* ad = (__half2*)&As[nxt][arow][acol];
            ad[0] = __floats2half2_rn(aReg.x, aReg.y);
            ad[1] = __floats2half2_rn(aReg.z, aReg.w);
            *(uint4*)&Bs[nxt][brow0][bc0] = bReg0;
            if (bp1) *(uint4*)&Bs[nxt][brow1][bc1] = bReg1;
        }
        __syncthreads();
    }

    // h stores (fp16)
#pragma unroll
    for (int mt = 0; mt < 2; mt++) {
        const int row0 = m0 + wm * 32 + mt * 16 + g;
#pragma unroll
        for (int nt = 0; nt < 10; nt++) {
            const int col = wn * 80 + nt * 8 + tg * 2;
            if (col < DHP) {
                *(__half2*)&g_h[(size_t)row0 * DHP + col]       = __floats2half2_rn(acc[mt][nt][0], acc[mt][nt][1]);
                *(__half2*)&g_h[(size_t)(row0 + 8) * DHP + col] = __floats2half2_rn(acc[mt][nt][2], acc[mt][nt][3]);
            }
        }
    }

    // fused BN1 column partials from fp32 accumulators (deterministic)
    float* sp = (float*)As;       // [4][320] sums, then [4][320] squares at +1280
#pragma unroll
    for (int nt = 0; nt < 10; nt++) {
        float s0 = 0.f, s1 = 0.f, q0 = 0.f, q1 = 0.f;
#pragma unroll
        for (int mt = 0; mt < 2; mt++) {
            const float v0 = acc[mt][nt][0], v1 = acc[mt][nt][1];
            const float v2 = acc[mt][nt][2], v3 = acc[mt][nt][3];
            s0 += v0 + v2;  s1 += v1 + v3;
            q0 += v0 * v0 + v2 * v2;  q1 += v1 * v1 + v3 * v3;
        }
#pragma unroll
        for (int o = 4; o < 32; o <<= 1) {
            s0 += __shfl_xor_sync(0xffffffffu, s0, o);
            s1 += __shfl_xor_sync(0xffffffffu, s1, o);
            q0 += __shfl_xor_sync(0xffffffffu, q0, o);
            q1 += __shfl_xor_sync(0xffffffffu, q1, o);
        }
        if (g == 0) {
            const int col = wn * 80 + nt * 8 + tg * 2;
            sp[wm * 320 + col]           = s0;
            sp[wm * 320 + col + 1]       = s1;
            sp[1280 + wm * 320 + col]    = q0;
            sp[1280 + wm * 320 + col + 1] = q1;
        }
    }
    __syncthreads();
    if (tid < DHP) {
        float s = 0.f, q = 0.f;
#pragma unroll
        for (int w = 0; w < 4; w++) { s += sp[w * 320 + tid]; q += sp[1280 + w * 320 + tid]; }
        g_part1s[tid * G1_BLOCKS + blockIdx.x] = s;
        g_part1q[tid * G1_BLOCKS + blockIdx.x] = q;
    }
}

// ---------------- reduce1: one block per column, coalesced -----------------
__global__ void reduce1_kernel(const float* __restrict__ gamma1, const float* __restrict__ beta1) {
    __shared__ float ss[8], qq[8];
    const int col = blockIdx.x, t = threadIdx.x;   // 256 threads
    float s = g_part1s[col * G1_BLOCKS + t] + g_part1s[col * G1_BLOCKS + t + 256];
    float q = g_part1q[col * G1_BLOCKS + t] + g_part1q[col * G1_BLOCKS + t + 256];
#pragma unroll
    for (int o = 16; o > 0; o >>= 1) {
        s += __shfl_xor_sync(0xffffffffu, s, o);
        q += __shfl_xor_sync(0xffffffffu, q, o);
    }
    if ((t & 31) == 0) { ss[t >> 5] = s; qq[t >> 5] = q; }
    __syncthreads();
    if (t == 0) {
        float S = 0.f, Q = 0.f;
#pragma unroll
        for (int w = 0; w < 8; w++) { S += ss[w]; Q += qq[w]; }
        const float inv = 1.f / (float)B_ROWS;
        const float mean = S * inv;
        const float var  = Q * inv - mean * mean;
        float a = 0.f, b = 0.f;
        if (col < D_H) {
            a = gamma1[col] * rsqrtf(var + EPSV);
            b = beta1[col] - mean * a;
        }
        g_ab1[col] = a;
        g_ab1[DHP + col] = b;
    }
}

// ---------------- GEMM2 (HMMA): o = BN1(h) @ sign(W2)^T + BN2 partials ----
// Block 128 rows x 16 cols (10 real), K=304 in 19 k16 steps. BN1 affine is
// applied while staging the A tile (fp32 fma, then cvt fp16).
__global__ __launch_bounds__(256, 1) void gemm2_kernel(float* __restrict__ out) {
    __shared__ __align__(16) __half As2[2][128][24];  // 12,288 B
    __shared__ __align__(16) __half Bs2[16][312];     //  9,984 B (312 stride: conflict-free + 16B aligned)
    __shared__ float sa[DHP], sb[DHP];
    __shared__ float ps[8][12], qs[8][12];

    const int tid = threadIdx.x;
    const int wid = tid >> 5, lane = tid & 31;
    const int g = lane >> 2, tg = lane & 3;
    const int m0 = blockIdx.x * 128;

    // load W2 tile (once, covers all K) + BN1 affine
    for (int i = tid; i < 16 * 38; i += 256) {
        const int r = i / 38, c = (i % 38) * 8;
        *(uint4*)&Bs2[r][c] = *(const uint4*)(g_B2h + r * DHP + c);
    }
    for (int i = tid; i < DHP; i += 256) { sa[i] = g_ab1[i]; sb[i] = g_ab1[DHP + i]; }
    __syncthreads();

    const int arow = tid >> 1, acol = (tid & 1) * 8;   // 8 halves per thread per iter
    const __half* aBase = g_h + (size_t)(m0 + arow) * DHP + acol;

    float acc[2][4];
#pragma unroll
    for (int nt = 0; nt < 2; nt++)
#pragma unroll
        for (int e = 0; e < 4; e++) acc[nt][e] = 0.f;

    uint4 aReg = *(const uint4*)aBase;

    // stage helper (manual): convert 8 halves with affine -> fp16 smem
#define STAGE_A(S, KB)                                                          \
    do {                                                                        \
        const int k0 = (KB) * 16 + acol;                                        \
        const __half2* hv = (const __half2*)&aReg;                              \
        __half2 o[4];                                                           \
        _Pragma("unroll")                                                       \
        for (int i2 = 0; i2 < 4; i2++) {                                        \
            float2 f = __half22float2(hv[i2]);                                  \
            const int k = k0 + i2 * 2;                                          \
            o[i2] = __floats2half2_rn(fmaf(f.x, sa[k], sb[k]),                  \
                                      fmaf(f.y, sa[k + 1], sb[k + 1]));         \
        }                                                                       \
        *(uint4*)&As2[S][arow][acol] = *(uint4*)o;                              \
    } while (0)

    STAGE_A(0, 0);
    __syncthreads();

    const int NK2 = DHP / 16;   // 19
    for (int kb = 0; kb < NK2; kb++) {
        const int cur = kb & 1;
        if (kb < NK2 - 1) aReg = *(const uint4*)(aBase + (kb + 1) * 16);

        const int ra = wid * 16 + g;
        const uint32_t a0 = *(const uint32_t*)&As2[cur][ra    ][tg * 2    ];
        const uint32_t a1 = *(const uint32_t*)&As2[cur][ra + 8][tg * 2    ];
        const uint32_t a2 = *(const uint32_t*)&As2[cur][ra    ][tg * 2 + 8];
        const uint32_t a3 = *(const uint32_t*)&As2[cur][ra + 8][tg * 2 + 8];
#pragma unroll
        for (int nt = 0; nt < 2; nt++) {
            const int rb = nt * 8 + g;
            const uint32_t b0v = *(const uint32_t*)&Bs2[rb][kb * 16 + tg * 2    ];
            const uint32_t b1v = *(const uint32_t*)&Bs2[rb][kb * 16 + tg * 2 + 8];
            MMA16816(acc[nt], a0, a1, a2, a3, b0v, b1v);
        }
        if (kb < NK2 - 1) STAGE_A(cur ^ 1, kb + 1);
        __syncthreads();
    }

    // store outputs (cols < 10)
    const int row0 = m0 + wid * 16 + g;
    {
        const int c0 = tg * 2;                 // nt=0: cols 0..7
        *(float2*)&out[(size_t)row0 * D_OUT + c0]       = make_float2(acc[0][0], acc[0][1]);
        *(float2*)&out[(size_t)(row0 + 8) * D_OUT + c0] = make_float2(acc[0][2], acc[0][3]);
        if (tg == 0) {                         // nt=1: cols 8,9
            *(float2*)&out[(size_t)row0 * D_OUT + 8]       = make_float2(acc[1][0], acc[1][1]);
            *(float2*)&out[(size_t)(row0 + 8) * D_OUT + 8] = make_float2(acc[1][2], acc[1][3]);
        }
    }

    // BN2 partials over this block's 128 rows (deterministic)
#pragma unroll
    for (int nt = 0; nt < 2; nt++) {
        float s0 = acc[nt][0] + acc[nt][2];
        float s1 = acc[nt][1] + acc[nt][3];
        float q0 = acc[nt][0] * acc[nt][0] + acc[nt][2] * acc[nt][2];
        float q1 = acc[nt][1] * acc[nt][1] + acc[nt][3] * acc[nt][3];
#pragma unroll
        for (int o = 4; o < 32; o <<= 1) {
            s0 += __shfl_xor_sync(0xffffffffu, s0, o);
            s1 += __shfl_xor_sync(0xffffffffu, s1, o);
            q0 += __shfl_xor_sync(0xffffffffu, q0, o);
            q1 += __shfl_xor_sync(0xffffffffu, q1, o);
        }
        if (g == 0) {
            const int c0 = nt * 8 + tg * 2;
            if (c0 < D_OUT) {
                ps[wid][c0] = s0; ps[wid][c0 + 1] = s1;
                qs[wid][c0] = q0; qs[wid][c0 + 1] = q1;
            }
        }
    }
    __syncthreads();
    if (tid < D_OUT) {
        float s = 0.f, q = 0.f;
#pragma unroll
        for (int w = 0; w < 8; w++) { s += ps[w][tid]; q += qs[w][tid]; }
        g_part2[blockIdx.x * 20 + tid] = s;
        g_part2[blockIdx.x * 20 + D_OUT + tid] = q;
    }
#undef STAGE_A
}

__global__ void reduce2_kernel(const float* __restrict__ gamma2, const float* __restrict__ beta2) {
    __shared__ float ss[256], qq[256];
    const int t = threadIdx.x, j = blockIdx.x;   // grid = 10
    float s = 0.f, q = 0.f;
    for (int i = t; i < G2_BLOCKS; i += 256) {
        s += g_part2[i * 20 + j];
        q += g_part2[i * 20 + D_OUT + j];
    }
    ss[t] = s; qq[t] = q; __syncthreads();
    for (int o = 128; o > 0; o >>= 1) {
        if (t < o) { ss[t] += ss[t + o]; qq[t] += qq[t + o]; }
        __syncthreads();
    }
    if (t == 0) {
        const float inv = 1.f / (float)B_ROWS;
        const float mean = ss[0] * inv;
        const float var  = qq[0] * inv - mean * mean;
        const float a = gamma2[j] * rsqrtf(var + EPSV);
        g_ab2[j] = a;
        g_ab2[D_OUT + j] = beta2[j] - mean * a;
    }
}

__global__ void apply_kernel(float* __restrict__ out) {
    const int i = blockIdx.x * blockDim.x + threadIdx.x;
    if (i < B_ROWS * D_OUT) {
        const int j = i % D_OUT;
        out[i] = fmaf(out[i], g_ab2[j], g_ab2[D_OUT + j]);
    }
}

// ---------------- launch ---------------------------------------------------
extern "C" void kernel_launch(void* const* d_in, const int* in_sizes, int n_in,
                              void* d_out, int out_size) {
    const float* x      = (const float*)d_in[0];
    const float* W1     = (const float*)d_in[1];
    const float* gamma1 = (const float*)d_in[2];
    const float* beta1  = (const float*)d_in[3];
    const float* W2     = (const float*)d_in[4];
    const float* gamma2 = (const float*)d_in[5];
    const float* beta2  = (const float*)d_in[6];
    float* out = (float*)d_out;

    const int prepN = BNP * D_IN + 16 * DHP;
    prep_kernel<<<(prepN + 255) / 256, 256>>>(W1, W2);
    gemm1_kernel<<<G1_BLOCKS, 512>>>(x);
    reduce1_kernel<<<DHP, 256>>>(gamma1, beta1);
    gemm2_kernel<<<G2_BLOCKS, 256>>>(out);
    reduce2_kernel<<<D_OUT, 256>>>(gamma2, beta2);
    apply_kernel<<<(B_ROWS * D_OUT + 255) / 256, 256>>>(out);
}

// round 5
// speedup vs baseline: 1.6266x; 1.2804x over previous
#include <cuda_runtime.h>
#include <cuda_fp16.h>
#include <cstdint>

#define B_ROWS 65536
#define D_IN   784
#define KP     800      // K padded to 25 slabs of 32
#define D_H    300
#define DHP    304      // padded h width (stride)
#define BNP    320      // padded binarized-W1 rows
#define D_OUT  10
#define EPSV   1e-5f
#define G1_BLOCKS (B_ROWS / 128)   // 512
#define G2_BLOCKS (B_ROWS / 128)   // 512
#define NSLAB  25

// ---------------- scratch ---------------------------------------------------
__device__ __align__(16) __half g_Bh1[BNP * KP];            // sign(W1) fp16, zero-padded
__device__ __align__(16) __half g_B2h[16 * DHP];            // sign(W2) fp16 16x304
__device__ __align__(16) __half g_h[(size_t)B_ROWS * DHP];  // layer-1 pre-BN output
__device__ __align__(16) float  g_part1s[DHP * G1_BLOCKS];
__device__ __align__(16) float  g_part1q[DHP * G1_BLOCKS];
__device__ __align__(16) float  g_ab1[2 * DHP];
__device__ __align__(16) float  g_part2[G2_BLOCKS * 20];
__device__ __align__(16) float  g_ab2[2 * D_OUT];

__device__ __forceinline__ uint32_t smem_u32(const void* p) {
    uint32_t a;
    asm("{ .reg .u64 t; cvta.to.shared.u64 t, %1; cvt.u32.u64 %0, t; }" : "=r"(a) : "l"(p));
    return a;
}

#define MMA16816(acc, a0,a1,a2,a3, b0,b1)                                      \
    asm volatile(                                                              \
        "mma.sync.aligned.m16n8k16.row.col.f32.f16.f16.f32 "                   \
        "{%0,%1,%2,%3}, {%4,%5,%6,%7}, {%8,%9}, {%0,%1,%2,%3};\n"              \
        : "+f"(acc[0]), "+f"(acc[1]), "+f"(acc[2]), "+f"(acc[3])               \
        : "r"(a0), "r"(a1), "r"(a2), "r"(a3), "r"(b0), "r"(b1))

#define LDSM_X4(r0,r1,r2,r3, addr)                                             \
    asm volatile("ldmatrix.sync.aligned.m8n8.x4.shared.b16 {%0,%1,%2,%3}, [%4];" \
        : "=r"(r0), "=r"(r1), "=r"(r2), "=r"(r3) : "r"(addr))

// ---------------- prep: binarize weights ----------------------------------
__global__ void prep_kernel(const float* __restrict__ W1, const float* __restrict__ W2) {
    int i = blockIdx.x * blockDim.x + threadIdx.x;
    const int n1 = BNP * KP;
    if (i < n1) {
        int n = i / KP, k = i - n * KP;
        float v = 0.f;
        if (n < D_H && k < D_IN) v = (W1[n * D_IN + k] >= 0.f) ? 1.f : -1.f;
        g_Bh1[i] = __float2half_rn(v);
    } else {
        int j = i - n1;
        if (j < 16 * DHP) {
            int r = j / DHP, c = j - r * DHP;
            float v = 0.f;
            if (r < D_OUT && c < D_H) v = (W2[r * D_H + c] >= 0.f) ? 1.f : -1.f;
            g_B2h[j] = __float2half_rn(v);
        }
    }
}

// ---------------- GEMM1: h = x @ sign(W1)^T + fused BN1 partials ----------
// 128x320 tile, BK=32 double-buffered, 512 threads (16 warps 4m x 4n).
// ldmatrix.x4 fragment loads, one sync per slab. Row stride 80B (conflict-free
// LDSM: r*80 mod 128 distinct for r=0..7).
//
// dyn smem layout (bytes):
//   A0 @ 0      (128 rows x 80B = 10240)    data: 64B/row (32 halves)
//   A1 @ 10240
//   B0 @ 20480  (320 rows x 80B = 25600)    data: 64B/row
//   B1 @ 46080
#define SMEM1_TOTAL (20480 + 2 * 25600)

__global__ __launch_bounds__(512, 1) void gemm1_kernel(const float* __restrict__ x) {
    extern __shared__ __align__(128) char smem[];
    const uint32_t sb = smem_u32(smem);
    const int tid  = threadIdx.x;
    const int wid  = tid >> 5, lane = tid & 31;
    const int wm   = wid & 3,  wn   = wid >> 2;
    const int g    = lane >> 2, tg  = lane & 3;
    const int m0   = blockIdx.x * 128;

    float acc[2][10][4];
#pragma unroll
    for (int mt = 0; mt < 2; mt++)
#pragma unroll
        for (int nt = 0; nt < 10; nt++)
#pragma unroll
            for (int e = 0; e < 4; e++) acc[mt][nt][e] = 0.f;

    // ldmatrix base addresses (verified lane->fragment maps for m16n8k16)
    const uint32_t aAddr = sb + (uint32_t)((wm * 32 + (lane & 15)) * 80 + (lane >> 4) * 16);
    const uint32_t bAddr = sb + 20480u
        + (uint32_t)((wn * 80 + (lane & 7) + ((lane >> 4) << 3)) * 80 + ((lane >> 3) & 1) * 16);

    const float* xBase = x + (size_t)m0 * D_IN;
    float4 aR[2];
    uint4  bR[3];

    // B slab = 320 rows x 32 halves = 1280 uint4. u -> (row=u>>2, quad=u&3).
#define LDG_SLAB(S)                                                              \
    do {                                                                         \
        const int kb = (S) * 32;                                                 \
        _Pragma("unroll")                                                        \
        for (int j = 0; j < 2; j++) {                                            \
            const int e = tid + 512 * j, row = e >> 3, c4 = (e & 7) * 4;         \
            aR[j] = (kb + c4 < D_IN)                                             \
                ? *(const float4*)(xBase + (size_t)row * D_IN + kb + c4)         \
                : make_float4(0.f, 0.f, 0.f, 0.f);                               \
        }                                                                        \
        _Pragma("unroll")                                                        \
        for (int j = 0; j < 2; j++) {                                            \
            const int u = tid + 512 * j;                                         \
            bR[j] = *(const uint4*)(g_Bh1 + (size_t)(u >> 2) * KP + kb + (u & 3) * 8); \
        }                                                                        \
        if (tid < 256) {                                                         \
            const int u = 1024 + tid;                                            \
            bR[2] = *(const uint4*)(g_Bh1 + (size_t)(u >> 2) * KP + kb + (u & 3) * 8); \
        }                                                                        \
    } while (0)

#define STS_SLAB(BUF)                                                            \
    do {                                                                         \
        const uint32_t aoff = (BUF) * 10240u;                                    \
        const uint32_t boff = 20480u + (BUF) * 25600u;                           \
        _Pragma("unroll")                                                        \
        for (int j = 0; j < 2; j++) {                                            \
            const int e = tid + 512 * j, row = e >> 3, c4 = (e & 7) * 4;         \
            __half2 h0 = __floats2half2_rn(aR[j].x, aR[j].y);                    \
            __half2 h1 = __floats2half2_rn(aR[j].z, aR[j].w);                    \
            uint2 v;                                                             \
            v.x = *(uint32_t*)&h0; v.y = *(uint32_t*)&h1;                        \
            *(uint2*)(smem + aoff + row * 80 + c4 * 2) = v;                      \
        }                                                                        \
        _Pragma("unroll")                                                        \
        for (int j = 0; j < 2; j++) {                                            \
            const int u = tid + 512 * j;                                         \
            *(uint4*)(smem + boff + (u >> 2) * 80 + (u & 3) * 16) = bR[j];       \
        }                                                                        \
        if (tid < 256) {                                                         \
            const int u = 1024 + tid;                                            \
            *(uint4*)(smem + boff + (u >> 2) * 80 + (u & 3) * 16) = bR[2];       \
        }                                                                        \
    } while (0)

#define COMPUTE_SLAB(BUF)                                                        \
    do {                                                                         \
        const uint32_t ab = aAddr + (BUF) * 10240u;                              \
        const uint32_t bb = bAddr + (BUF) * 25600u;                              \
        _Pragma("unroll")                                                        \
        for (int kk = 0; kk < 2; kk++) {                                         \
            uint32_t a0[4], a1[4];                                               \
            LDSM_X4(a0[0], a0[1], a0[2], a0[3], ab + kk * 32);                   \
            LDSM_X4(a1[0], a1[1], a1[2], a1[3], ab + 1280 + kk * 32);            \
            _Pragma("unroll")                                                    \
            for (int p = 0; p < 5; p++) {                                        \
                uint32_t b0, b1, b2, b3;                                         \
                LDSM_X4(b0, b1, b2, b3, bb + p * 1280 + kk * 32);                \
                MMA16816(acc[0][2 * p],     a0[0], a0[1], a0[2], a0[3], b0, b1); \
                MMA16816(acc[1][2 * p],     a1[0], a1[1], a1[2], a1[3], b0, b1); \
                MMA16816(acc[0][2 * p + 1], a0[0], a0[1], a0[2], a0[3], b2, b3); \
                MMA16816(acc[1][2 * p + 1], a1[0], a1[1], a1[2], a1[3], b2, b3); \
            }                                                                    \
        }                                                                        \
    } while (0)

    LDG_SLAB(0);
    STS_SLAB(0);
    __syncthreads();
    for (int s = 0; s < NSLAB; s++) {
        const int buf = s & 1;
        if (s < NSLAB - 1) LDG_SLAB(s + 1);
        COMPUTE_SLAB(buf);
        if (s < NSLAB - 1) STS_SLAB(buf ^ 1);
        __syncthreads();
    }
#undef LDG_SLAB
#undef STS_SLAB
#undef COMPUTE_SLAB

    // h stores (fp16)
#pragma unroll
    for (int mt = 0; mt < 2; mt++) {
        const int row0 = m0 + wm * 32 + mt * 16 + g;
#pragma unroll
        for (int nt = 0; nt < 10; nt++) {
            const int col = wn * 80 + nt * 8 + tg * 2;
            if (col < DHP) {
                *(__half2*)&g_h[(size_t)row0 * DHP + col]       = __floats2half2_rn(acc[mt][nt][0], acc[mt][nt][1]);
                *(__half2*)&g_h[(size_t)(row0 + 8) * DHP + col] = __floats2half2_rn(acc[mt][nt][2], acc[mt][nt][3]);
            }
        }
    }

    // fused BN1 column partials from fp32 accumulators (deterministic)
    float* sp = (float*)smem;      // [4][320] sums, then [4][320] squares at +1280
#pragma unroll
    for (int nt = 0; nt < 10; nt++) {
        float s0 = 0.f, s1 = 0.f, q0 = 0.f, q1 = 0.f;
#pragma unroll
        for (int mt = 0; mt < 2; mt++) {
            const float v0 = acc[mt][nt][0], v1 = acc[mt][nt][1];
            const float v2 = acc[mt][nt][2], v3 = acc[mt][nt][3];
            s0 += v0 + v2;  s1 += v1 + v3;
            q0 += v0 * v0 + v2 * v2;  q1 += v1 * v1 + v3 * v3;
        }
#pragma unroll
        for (int o = 4; o < 32; o <<= 1) {
            s0 += __shfl_xor_sync(0xffffffffu, s0, o);
            s1 += __shfl_xor_sync(0xffffffffu, s1, o);
            q0 += __shfl_xor_sync(0xffffffffu, q0, o);
            q1 += __shfl_xor_sync(0xffffffffu, q1, o);
        }
        if (g == 0) {
            const int col = wn * 80 + nt * 8 + tg * 2;
            sp[wm * 320 + col]            = s0;
            sp[wm * 320 + col + 1]        = s1;
            sp[1280 + wm * 320 + col]     = q0;
            sp[1280 + wm * 320 + col + 1] = q1;
        }
    }
    __syncthreads();
    if (tid < DHP) {
        float s = 0.f, q = 0.f;
#pragma unroll
        for (int w = 0; w < 4; w++) { s += sp[w * 320 + tid]; q += sp[1280 + w * 320 + tid]; }
        g_part1s[(size_t)tid * G1_BLOCKS + blockIdx.x] = s;
        g_part1q[(size_t)tid * G1_BLOCKS + blockIdx.x] = q;
    }
}

// ---------------- reduce1 ---------------------------------------------------
__global__ void reduce1_kernel(const float* __restrict__ gamma1, const float* __restrict__ beta1) {
    __shared__ float ss[8], qq[8];
    const int col = blockIdx.x, t = threadIdx.x;   // 256 threads
    float s = g_part1s[(size_t)col * G1_BLOCKS + t] + g_part1s[(size_t)col * G1_BLOCKS + t + 256];
    float q = g_part1q[(size_t)col * G1_BLOCKS + t] + g_part1q[(size_t)col * G1_BLOCKS + t + 256];
#pragma unroll
    for (int o = 16; o > 0; o >>= 1) {
        s += __shfl_xor_sync(0xffffffffu, s, o);
        q += __shfl_xor_sync(0xffffffffu, q, o);
    }
    if ((t & 31) == 0) { ss[t >> 5] = s; qq[t >> 5] = q; }
    __syncthreads();
    if (t == 0) {
        float S = 0.f, Q = 0.f;
#pragma unroll
        for (int w = 0; w < 8; w++) { S += ss[w]; Q += qq[w]; }
        const float inv = 1.f / (float)B_ROWS;
        const float mean = S * inv;
        const float var  = Q * inv - mean * mean;
        float a = 0.f, b = 0.f;
        if (col < D_H) {
            a = gamma1[col] * rsqrtf(var + EPSV);
            b = beta1[col] - mean * a;
        }
        g_ab1[col] = a;
        g_ab1[DHP + col] = b;
    }
}

// ---------------- GEMM2 (HMMA): o = BN1(h) @ sign(W2)^T + BN2 partials ----
__global__ __launch_bounds__(256, 1) void gemm2_kernel(float* __restrict__ out) {
    __shared__ __align__(16) __half As2[2][128][24];
    __shared__ __align__(16) __half Bs2[16][312];
    __shared__ float sa[DHP], sb2[DHP];
    __shared__ float ps[8][12], qs[8][12];

    const int tid = threadIdx.x;
    const int wid = tid >> 5, lane = tid & 31;
    const int g = lane >> 2, tg = lane & 3;
    const int m0 = blockIdx.x * 128;

    for (int i = tid; i < 16 * 38; i += 256) {
        const int r = i / 38, c = (i % 38) * 8;
        *(uint4*)&Bs2[r][c] = *(const uint4*)(g_B2h + r * DHP + c);
    }
    for (int i = tid; i < DHP; i += 256) { sa[i] = g_ab1[i]; sb2[i] = g_ab1[DHP + i]; }
    __syncthreads();

    const int arow = tid >> 1, acol = (tid & 1) * 8;
    const __half* aBase = g_h + (size_t)(m0 + arow) * DHP + acol;

    float acc[2][4];
#pragma unroll
    for (int nt = 0; nt < 2; nt++)
#pragma unroll
        for (int e = 0; e < 4; e++) acc[nt][e] = 0.f;

    uint4 aReg = *(const uint4*)aBase;

#define STAGE_A(S, KB)                                                          \
    do {                                                                        \
        const int k0 = (KB) * 16 + acol;                                        \
        const __half2* hv = (const __half2*)&aReg;                              \
        __half2 o[4];                                                           \
        _Pragma("unroll")                                                       \
        for (int i2 = 0; i2 < 4; i2++) {                                        \
            float2 f = __half22float2(hv[i2]);                                  \
            const int k = k0 + i2 * 2;                                          \
            o[i2] = __floats2half2_rn(fmaf(f.x, sa[k], sb2[k]),                 \
                                      fmaf(f.y, sa[k + 1], sb2[k + 1]));        \
        }                                                                       \
        *(uint4*)&As2[S][arow][acol] = *(uint4*)o;                              \
    } while (0)

    STAGE_A(0, 0);
    __syncthreads();

    const int NK2 = DHP / 16;   // 19
    for (int kb = 0; kb < NK2; kb++) {
        const int cur = kb & 1;
        if (kb < NK2 - 1) aReg = *(const uint4*)(aBase + (kb + 1) * 16);
        const int ra = wid * 16 + g;
        const uint32_t a0 = *(const uint32_t*)&As2[cur][ra    ][tg * 2    ];
        const uint32_t a1 = *(const uint32_t*)&As2[cur][ra + 8][tg * 2    ];
        const uint32_t a2 = *(const uint32_t*)&As2[cur][ra    ][tg * 2 + 8];
        const uint32_t a3 = *(const uint32_t*)&As2[cur][ra + 8][tg * 2 + 8];
#pragma unroll
        for (int nt = 0; nt < 2; nt++) {
            const int rb = nt * 8 + g;
            const uint32_t b0v = *(const uint32_t*)&Bs2[rb][kb * 16 + tg * 2    ];
            const uint32_t b1v = *(const uint32_t*)&Bs2[rb][kb * 16 + tg * 2 + 8];
            MMA16816(acc[nt], a0, a1, a2, a3, b0v, b1v);
        }
        if (kb < NK2 - 1) STAGE_A(cur ^ 1, kb + 1);
        __syncthreads();
    }

    const int row0 = m0 + wid * 16 + g;
    {
        const int c0 = tg * 2;
        *(float2*)&out[(size_t)row0 * D_OUT + c0]       = make_float2(acc[0][0], acc[0][1]);
        *(float2*)&out[(size_t)(row0 + 8) * D_OUT + c0] = make_float2(acc[0][2], acc[0][3]);
        if (tg == 0) {
            *(float2*)&out[(size_t)row0 * D_OUT + 8]       = make_float2(acc[1][0], acc[1][1]);
            *(float2*)&out[(size_t)(row0 + 8) * D_OUT + 8] = make_float2(acc[1][2], acc[1][3]);
        }
    }
#pragma unroll
    for (int nt = 0; nt < 2; nt++) {
        float s0 = acc[nt][0] + acc[nt][2];
        float s1 = acc[nt][1] + acc[nt][3];
        float q0 = acc[nt][0] * acc[nt][0] + acc[nt][2] * acc[nt][2];
        float q1 = acc[nt][1] * acc[nt][1] + acc[nt][3] * acc[nt][3];
#pragma unroll
        for (int o = 4; o < 32; o <<= 1) {
            s0 += __shfl_xor_sync(0xffffffffu, s0, o);
            s1 += __shfl_xor_sync(0xffffffffu, s1, o);
            q0 += __shfl_xor_sync(0xffffffffu, q0, o);
            q1 += __shfl_xor_sync(0xffffffffu, q1, o);
        }
        if (g == 0) {
            const int c0 = nt * 8 + tg * 2;
            if (c0 < D_OUT) {
                ps[wid][c0] = s0; ps[wid][c0 + 1] = s1;
                qs[wid][c0] = q0; qs[wid][c0 + 1] = q1;
            }
        }
    }
    __syncthreads();
    if (tid < D_OUT) {
        float s = 0.f, q = 0.f;
#pragma unroll
        for (int w = 0; w < 8; w++) { s += ps[w][tid]; q += qs[w][tid]; }
        g_part2[blockIdx.x * 20 + tid] = s;
        g_part2[blockIdx.x * 20 + D_OUT + tid] = q;
    }
#undef STAGE_A
}

__global__ void reduce2_kernel(const float* __restrict__ gamma2, const float* __restrict__ beta2) {
    __shared__ float ss[256], qq[256];
    const int t = threadIdx.x, j = blockIdx.x;
    float s = 0.f, q = 0.f;
    for (int i = t; i < G2_BLOCKS; i += 256) {
        s += g_part2[i * 20 + j];
        q += g_part2[i * 20 + D_OUT + j];
    }
    ss[t] = s; qq[t] = q; __syncthreads();
    for (int o = 128; o > 0; o >>= 1) {
        if (t < o) { ss[t] += ss[t + o]; qq[t] += qq[t + o]; }
        __syncthreads();
    }
    if (t == 0) {
        const float inv = 1.f / (float)B_ROWS;
        const float mean = ss[0] * inv;
        const float var  = qq[0] * inv - mean * mean;
        const float a = gamma2[j] * rsqrtf(var + EPSV);
        g_ab2[j] = a;
        g_ab2[D_OUT + j] = beta2[j] - mean * a;
    }
}

__global__ void apply_kernel(float* __restrict__ out) {
    const int i = blockIdx.x * blockDim.x + threadIdx.x;
    if (i < B_ROWS * D_OUT) {
        const int j = i % D_OUT;
        out[i] = fmaf(out[i], g_ab2[j], g_ab2[D_OUT + j]);
    }
}

// ---------------- launch ---------------------------------------------------
extern "C" void kernel_launch(void* const* d_in, const int* in_sizes, int n_in,
                              void* d_out, int out_size) {
    const float* x      = (const float*)d_in[0];
    const float* W1     = (const float*)d_in[1];
    const float* gamma1 = (const float*)d_in[2];
    const float* beta1  = (const float*)d_in[3];
    const float* W2     = (const float*)d_in[4];
    const float* gamma2 = (const float*)d_in[5];
    const float* beta2  = (const float*)d_in[6];
    float* out = (float*)d_out;

    cudaFuncSetAttribute(gemm1_kernel, cudaFuncAttributeMaxDynamicSharedMemorySize, SMEM1_TOTAL);

    const int prepN = BNP * KP + 16 * DHP;
    prep_kernel<<<(prepN + 255) / 256, 256>>>(W1, W2);
    gemm1_kernel<<<G1_BLOCKS, 512, SMEM1_TOTAL>>>(x);
    reduce1_kernel<<<DHP, 256>>>(gamma1, beta1);
    gemm2_kernel<<<G2_BLOCKS, 256>>>(out);
    reduce2_kernel<<<D_OUT, 256>>>(gamma2, beta2);
    apply_kernel<<<(B_ROWS * D_OUT + 255) / 256, 256>>>(out);
}